// round 6
// baseline (speedup 1.0000x reference)
#include <cuda_runtime.h>
#include <math.h>

#define BB   256
#define NIN  64
#define HID  128
#define NOUT 64
#define TT   1000
#define NC   384   // z(128) | r(128) | h~(128)

// ---------------- scratch (static device memory; no allocations) -------------
__device__ float g_GX[TT * BB * NIN];          //  65.5 MB  gamma_x  [(t*B+b)*64 + i]
__device__ float g_GH[TT * BB * HID];          // 131.1 MB  gamma_h  [(t*B+b)*128 + j]
__device__ float g_XM[TT * BB * 128];          // 131.1 MB  [x_hat(64) | m(64)] per (t,b)
__device__ float g_U [TT * BB * NC];           // 393.2 MB  input projections
__device__ float g_Wcat[128 * NC];             // packed [x;m] -> [z|r|h~] weights
__device__ float g_bias[NC];

// ============================ K1: gamma GEMM =================================
// gamma = exp(-relu(d @ [W_dg_x | W_dg_h] + bias)), rows are (b,t) pairs.
#define K1_T 40
#define K1_SMEM ((64*192 + 192 + 64*K1_T) * 4)
__global__ void k1_gamma(const float* __restrict__ inp,
                         const float* __restrict__ Wdgx, const float* __restrict__ bdgx,
                         const float* __restrict__ Wdgh, const float* __restrict__ bdgh) {
    extern __shared__ float sm[];
    float* Wg   = sm;               // [64][192]
    float* bias = Wg + 64 * 192;    // [192]
    float* ds   = bias + 192;       // [64][K1_T]
    int tid = threadIdx.x;
    int b   = blockIdx.y;
    int t0  = blockIdx.x * K1_T;

    for (int idx = tid; idx < 64 * 192; idx += 256) {
        int k = idx / 192, j = idx % 192;
        Wg[idx] = (j < 64) ? Wdgx[k * 64 + j] : Wdgh[k * 128 + (j - 64)];
    }
    for (int j = tid; j < 192; j += 256)
        bias[j] = (j < 64) ? bdgx[j] : bdgh[j - 64];

    const float* dbase = inp + ((size_t)(b * 3 + 2) * NIN) * TT;
    for (int idx = tid; idx < 64 * (K1_T / 4); idx += 256) {
        int i = idx / (K1_T / 4), c = idx % (K1_T / 4);
        float4 v = *(const float4*)(dbase + (size_t)i * TT + t0 + c * 4);
        *(float4*)(ds + i * K1_T + c * 4) = v;
    }
    __syncthreads();

    for (int o = tid; o < K1_T * 192; o += 256) {
        int tt = o / 192, j = o % 192;
        float acc = bias[j];
        #pragma unroll 16
        for (int k = 0; k < 64; k++)
            acc += ds[k * K1_T + tt] * Wg[k * 192 + j];
        float g = (acc > 0.f) ? __expf(-acc) : 1.f;
        int t = t0 + tt;
        if (j < 64) g_GX[((t * BB + b) << 6) + j] = g;
        else        g_GH[((t * BB + b) << 7) + (j - 64)] = g;
    }
}

// ============================ K2: xl scan + x_hat ============================
__global__ void k2_scan(const float* __restrict__ inp, const float* __restrict__ xmean) {
    int gid = blockIdx.x * blockDim.x + threadIdx.x;   // 0..16383
    int b = gid >> 6, i = gid & 63;
    const float* X = inp + ((size_t)(b * 3 + 0) * NIN + i) * TT;
    const float* M = inp + ((size_t)(b * 3 + 1) * NIN + i) * TT;
    float xm = xmean[i];
    float xl = 0.f;
    for (int t = 0; t < TT; t++) {
        float x = X[t], m = M[t];
        float gx = g_GX[((t * BB + b) << 6) + i];
        if (m > 0.f) xl = x;
        float xh = m * x + (1.f - m) * (gx * xl + (1.f - gx) * xm);
        int base = ((t * BB + b) << 7);
        g_XM[base + i]      = xh;
        g_XM[base + 64 + i] = m;
    }
}

// ============================ K3: weight packing =============================
__global__ void k_pack(const float* __restrict__ Wxz, const float* __restrict__ Wmz,
                       const float* __restrict__ bmz,
                       const float* __restrict__ Wxr, const float* __restrict__ Wmr,
                       const float* __restrict__ Wxh, const float* __restrict__ Wmh,
                       const float* __restrict__ bmh) {
    int idx = blockIdx.x * 256 + threadIdx.x;
    if (idx < 128 * NC) {
        int k = idx / NC, j = idx % NC;
        float v;
        if (k < 64) {
            const float* W = (j < 128) ? Wxz : (j < 256) ? Wxr : Wxh;
            v = W[k * 128 + (j & 127)];
        } else {
            const float* W = (j < 128) ? Wmz : (j < 256) ? Wmr : Wmh;
            v = W[(k - 64) * 128 + (j & 127)];
        }
        g_Wcat[idx] = v;
    }
    if (idx < NC)
        g_bias[idx] = (idx < 128) ? bmz[idx] : (idx < 256) ? 0.f : bmh[idx - 256];
}

// ============================ K4: U GEMM =====================================
// U = XM @ Wcat + bias : M=256000, K=128, N=384
#define K4_ROWS 32
#define K4_SMEM ((128*NC + NC + K4_ROWS*128) * 4)
__global__ void k4_ugemm() {
    extern __shared__ float sm[];
    float* Ws = sm;                    // [128][384]
    float* bs = Ws + 128 * NC;         // [384]
    float* As = bs + NC;               // [32][128]
    int tid = threadIdx.x;

    for (int idx = tid; idx < 128 * NC / 4; idx += 256)
        *(float4*)(Ws + idx * 4) = *(const float4*)(g_Wcat + idx * 4);
    for (int j = tid; j < NC; j += 256) bs[j] = g_bias[j];

    int row0 = blockIdx.x * K4_ROWS;
    const float* A = g_XM + (size_t)row0 * 128;
    for (int idx = tid; idx < K4_ROWS * 128 / 4; idx += 256)
        *(float4*)(As + idx * 4) = *(const float4*)(A + idx * 4);
    __syncthreads();

    int cg = tid & 31;           // 32 col groups of 12
    int rg = tid >> 5;           // 8 row groups of 4
    int j0 = cg * 12, r0 = rg * 4;

    float acc[4][12];
    #pragma unroll
    for (int r = 0; r < 4; r++)
        #pragma unroll
        for (int c = 0; c < 12; c++) acc[r][c] = 0.f;

    #pragma unroll 4
    for (int k = 0; k < 128; k++) {
        float a0 = As[(r0 + 0) * 128 + k];
        float a1 = As[(r0 + 1) * 128 + k];
        float a2 = As[(r0 + 2) * 128 + k];
        float a3 = As[(r0 + 3) * 128 + k];
        const float* wrow = Ws + k * NC + j0;
        float4 w0 = *(const float4*)(wrow + 0);
        float4 w1 = *(const float4*)(wrow + 4);
        float4 w2 = *(const float4*)(wrow + 8);
        float w[12] = {w0.x, w0.y, w0.z, w0.w, w1.x, w1.y, w1.z, w1.w,
                       w2.x, w2.y, w2.z, w2.w};
        #pragma unroll
        for (int c = 0; c < 12; c++) {
            acc[0][c] += a0 * w[c];
            acc[1][c] += a1 * w[c];
            acc[2][c] += a2 * w[c];
            acc[3][c] += a3 * w[c];
        }
    }

    float* Ubase = g_U + (size_t)row0 * NC;
    #pragma unroll
    for (int r = 0; r < 4; r++)
        #pragma unroll
        for (int c = 0; c < 12; c++)
            Ubase[(size_t)(r0 + r) * NC + j0 + c] = acc[r][c] + bs[j0 + c];
}

// ============================ K5: sequential recurrence ======================
// 128 CTAs x 2 batch rows, 512 threads. W_hz|W_hr|W_hh resident in SMEM.
#define HSTR 132
#define K5_SMEM ((128*NC + 3*2*HSTR) * 4)
__global__ void k5_rec(const float* __restrict__ Whz, const float* __restrict__ Whr,
                       const float* __restrict__ Whh, float* __restrict__ hs_out) {
    extern __shared__ float sm[];
    float* Ws   = sm;                        // [128][384]  (k-major)
    float* h_s  = Ws + 128 * NC;             // [2][HSTR]
    float* rh_s = h_s + 2 * HSTR;            // [2][HSTR]
    float* ht_s = rh_s + 2 * HSTR;           // [2][HSTR]
    int tid = threadIdx.x;
    int b0  = blockIdx.x * 2;

    for (int idx = tid; idx < 128 * 128; idx += 512) {
        int k = idx >> 7, j = idx & 127;
        Ws[k * NC + j]       = Whz[idx];
        Ws[k * NC + 128 + j] = Whr[idx];
        Ws[k * NC + 256 + j] = Whh[idx];
    }
    if (tid < 256) h_s[(tid >> 7) * HSTR + (tid & 127)] = 0.f;
    __syncthreads();

    int grp = (tid < 256) ? 0 : 1;
    int lt  = tid & 255;
    int role_row = lt & 1;
    int role_j   = lt >> 1;

    // prefetched values
    float gh = 0.f, u_r = 0.f, u_h = 0.f, u_z = 0.f;
    if (grp == 0) {
        gh  = g_GH[((b0 + (tid >> 7)) << 7) + (tid & 127)];
        u_r = g_U[(size_t)(b0 + role_row) * NC + 128 + role_j];
        u_h = g_U[(size_t)(b0 + role_row) * NC + 256 + role_j];
    } else {
        u_z = g_U[(size_t)(b0 + role_row) * NC + role_j];
    }

    for (int t = 0; t < TT; t++) {
        int tn = (t + 1 < TT) ? (t + 1) : t;
        // (a) scale h by gamma_h
        if (grp == 0) {
            int sr = tid >> 7, sj = tid & 127;
            h_s[sr * HSTR + sj] *= gh;
        }
        __syncthreads();
        if (grp == 0)
            gh = g_GH[((tn * BB + b0 + (tid >> 7)) << 7) + (tid & 127)];

        float zval = 0.f, hold = 0.f;
        if (grp == 0) {
            // r gate -> rh
            const float* hrow = h_s + role_row * HSTR;
            const float* wc   = Ws + 128 + role_j;
            float acc = 0.f;
            #pragma unroll 16
            for (int k = 0; k < 128; k++) acc += hrow[k] * wc[k * NC];
            acc += u_r;
            float r = 1.f / (1.f + __expf(-acc));
            rh_s[role_row * HSTR + role_j] = r * hrow[role_j];
            u_r = g_U[(size_t)(tn * BB + b0 + role_row) * NC + 128 + role_j];
        } else {
            // z gate
            const float* hrow = h_s + role_row * HSTR;
            const float* wc   = Ws + role_j;
            float acc = 0.f;
            #pragma unroll 16
            for (int k = 0; k < 128; k++) acc += hrow[k] * wc[k * NC];
            acc += u_z;
            zval = 1.f / (1.f + __expf(-acc));
            hold = hrow[role_j];
            u_z = g_U[(size_t)(tn * BB + b0 + role_row) * NC + role_j];
        }
        __syncthreads();
        if (grp == 0) {
            // h~ = tanh(U_h + (r*h) @ W_hh)
            const float* rrow = rh_s + role_row * HSTR;
            const float* wc   = Ws + 256 + role_j;
            float acc = 0.f;
            #pragma unroll 16
            for (int k = 0; k < 128; k++) acc += rrow[k] * wc[k * NC];
            acc += u_h;
            ht_s[role_row * HSTR + role_j] = tanhf(acc);
            u_h = g_U[(size_t)(tn * BB + b0 + role_row) * NC + 256 + role_j];
        }
        __syncthreads();
        if (grp == 1) {
            float ht = ht_s[role_row * HSTR + role_j];
            float hn = (1.f - zval) * hold + zval * ht;
            h_s[role_row * HSTR + role_j] = hn;
            hs_out[((size_t)(b0 + role_row) * TT + t) * HID + role_j] = hn;
        }
        __syncthreads();
    }
}

// ============================ K6: y epilogue GEMM ============================
__global__ void k6_y(const float* __restrict__ Why, const float* __restrict__ bhy,
                     const float* __restrict__ hs, float* __restrict__ ys) {
    __shared__ float Ws[128 * 64];
    __shared__ float bs[64];
    __shared__ float As[16 * 128];
    int tid = threadIdx.x;
    for (int idx = tid; idx < 128 * 64; idx += 256) Ws[idx] = Why[idx];
    if (tid < 64) bs[tid] = bhy[tid];
    int row0 = blockIdx.x * 16;
    for (int idx = tid; idx < 16 * 128 / 4; idx += 256)
        *(float4*)(As + idx * 4) = *(const float4*)(hs + (size_t)row0 * 128 + idx * 4);
    __syncthreads();

    int col = tid & 63, rg = tid >> 6;   // 4 row groups of 4 rows
    float a0 = 0.f, a1 = 0.f, a2 = 0.f, a3 = 0.f;
    #pragma unroll 8
    for (int k = 0; k < 128; k++) {
        float w = Ws[k * 64 + col];
        a0 += As[(rg * 4 + 0) * 128 + k] * w;
        a1 += As[(rg * 4 + 1) * 128 + k] * w;
        a2 += As[(rg * 4 + 2) * 128 + k] * w;
        a3 += As[(rg * 4 + 3) * 128 + k] * w;
    }
    float b = bs[col];
    size_t obase = (size_t)(row0 + rg * 4) * 64 + col;
    ys[obase + 0 * 64] = 1.f / (1.f + __expf(-(a0 + b)));
    ys[obase + 1 * 64] = 1.f / (1.f + __expf(-(a1 + b)));
    ys[obase + 2 * 64] = 1.f / (1.f + __expf(-(a2 + b)));
    ys[obase + 3 * 64] = 1.f / (1.f + __expf(-(a3 + b)));
}

// ============================ launch =========================================
extern "C" void kernel_launch(void* const* d_in, const int* in_sizes, int n_in,
                              void* d_out, int out_size) {
    const float* inp   = (const float*)d_in[0];
    const float* xmean = (const float*)d_in[1];
    const float* Wdgx  = (const float*)d_in[2];
    const float* bdgx  = (const float*)d_in[3];
    const float* Wdgh  = (const float*)d_in[4];
    const float* bdgh  = (const float*)d_in[5];
    const float* Wxz   = (const float*)d_in[6];
    const float* Whz   = (const float*)d_in[7];
    const float* Wmz   = (const float*)d_in[8];
    const float* bmz   = (const float*)d_in[9];
    const float* Wxr   = (const float*)d_in[10];
    const float* Whr   = (const float*)d_in[11];
    const float* Wmr   = (const float*)d_in[12];
    const float* Wxh   = (const float*)d_in[13];
    const float* Whh   = (const float*)d_in[14];
    const float* Wmh   = (const float*)d_in[15];
    const float* bmh   = (const float*)d_in[16];
    const float* Why   = (const float*)d_in[17];
    const float* bhy   = (const float*)d_in[18];

    float* ys = (float*)d_out;                              // (B, T, 64)
    float* hs = (float*)d_out + (size_t)BB * TT * NOUT;     // (B, T, 128)

    cudaFuncSetAttribute(k1_gamma, cudaFuncAttributeMaxDynamicSharedMemorySize, K1_SMEM);
    cudaFuncSetAttribute(k4_ugemm, cudaFuncAttributeMaxDynamicSharedMemorySize, K4_SMEM);
    cudaFuncSetAttribute(k5_rec,   cudaFuncAttributeMaxDynamicSharedMemorySize, K5_SMEM);

    k1_gamma<<<dim3(TT / K1_T, BB), 256, K1_SMEM>>>(inp, Wdgx, bdgx, Wdgh, bdgh);
    k2_scan<<<64, 256>>>(inp, xmean);
    k_pack<<<(128 * NC + 255) / 256, 256>>>(Wxz, Wmz, bmz, Wxr, Wmr, Wxh, Wmh, bmh);
    k4_ugemm<<<TT * BB / K4_ROWS, 256, K4_SMEM>>>();
    k5_rec<<<BB / 2, 512, K5_SMEM>>>(Whz, Whr, Whh, hs);
    k6_y<<<TT * BB / 16, 256>>>(Why, bhy, hs, ys);
}

// round 8
// speedup vs baseline: 1.0017x; 1.0017x over previous
#include <cuda_runtime.h>
#include <math.h>

#define BB   256
#define NIN  64
#define HID  128
#define NOUT 64
#define TT   1000
#define NC   384   // z(128) | r(128) | h~(128)

// ---------------- scratch (static device memory; no allocations) -------------
__device__ float g_GX[TT * BB * NIN];          //  65.5 MB  gamma_x  [(t*B+b)*64 + i]
__device__ float g_GH[TT * BB * HID];          // 131.1 MB  gamma_h  [(t*B+b)*128 + j]
__device__ float g_XM[TT * BB * 128];          // 131.1 MB  [x_hat(64) | m(64)] per (t,b)
__device__ float g_U [TT * BB * NC];           // 393.2 MB  input projections
__device__ float g_Wcat[128 * NC];             // packed [x;m] -> [z|r|h~] weights
__device__ float g_bias[NC];

// ============================ K1: gamma GEMM =================================
// gamma = exp(-relu(d @ [W_dg_x | W_dg_h] + bias)), rows are (b,t) pairs.
#define K1_T 40
#define K1_SMEM ((64*192 + 192 + 64*K1_T) * 4)
__global__ void k1_gamma(const float* __restrict__ inp,
                         const float* __restrict__ Wdgx, const float* __restrict__ bdgx,
                         const float* __restrict__ Wdgh, const float* __restrict__ bdgh) {
    extern __shared__ float sm[];
    float* Wg   = sm;               // [64][192]
    float* bias = Wg + 64 * 192;    // [192]
    float* ds   = bias + 192;       // [64][K1_T]
    int tid = threadIdx.x;
    int b   = blockIdx.y;
    int t0  = blockIdx.x * K1_T;

    for (int idx = tid; idx < 64 * 192; idx += 256) {
        int k = idx / 192, j = idx % 192;
        Wg[idx] = (j < 64) ? Wdgx[k * 64 + j] : Wdgh[k * 128 + (j - 64)];
    }
    for (int j = tid; j < 192; j += 256)
        bias[j] = (j < 64) ? bdgx[j] : bdgh[j - 64];

    const float* dbase = inp + ((size_t)(b * 3 + 2) * NIN) * TT;
    for (int idx = tid; idx < 64 * (K1_T / 4); idx += 256) {
        int i = idx / (K1_T / 4), c = idx % (K1_T / 4);
        float4 v = *(const float4*)(dbase + (size_t)i * TT + t0 + c * 4);
        *(float4*)(ds + i * K1_T + c * 4) = v;
    }
    __syncthreads();

    for (int o = tid; o < K1_T * 192; o += 256) {
        int tt = o / 192, j = o % 192;
        float acc = bias[j];
        #pragma unroll 16
        for (int k = 0; k < 64; k++)
            acc += ds[k * K1_T + tt] * Wg[k * 192 + j];
        float g = (acc > 0.f) ? __expf(-acc) : 1.f;
        int t = t0 + tt;
        if (j < 64) g_GX[((t * BB + b) << 6) + j] = g;
        else        g_GH[((t * BB + b) << 7) + (j - 64)] = g;
    }
}

// ============================ K2: xl scan + x_hat ============================
__global__ void k2_scan(const float* __restrict__ inp, const float* __restrict__ xmean) {
    int gid = blockIdx.x * blockDim.x + threadIdx.x;   // 0..16383
    int b = gid >> 6, i = gid & 63;
    const float* X = inp + ((size_t)(b * 3 + 0) * NIN + i) * TT;
    const float* M = inp + ((size_t)(b * 3 + 1) * NIN + i) * TT;
    float xm = xmean[i];
    float xl = 0.f;
    for (int t = 0; t < TT; t++) {
        float x = X[t], m = M[t];
        float gx = g_GX[((t * BB + b) << 6) + i];
        if (m > 0.f) xl = x;
        float xh = m * x + (1.f - m) * (gx * xl + (1.f - gx) * xm);
        int base = ((t * BB + b) << 7);
        g_XM[base + i]      = xh;
        g_XM[base + 64 + i] = m;
    }
}

// ============================ K3: weight packing =============================
__global__ void k_pack(const float* __restrict__ Wxz, const float* __restrict__ Wmz,
                       const float* __restrict__ bmz,
                       const float* __restrict__ Wxr, const float* __restrict__ Wmr,
                       const float* __restrict__ Wxh, const float* __restrict__ Wmh,
                       const float* __restrict__ bmh) {
    int idx = blockIdx.x * 256 + threadIdx.x;
    if (idx < 128 * NC) {
        int k = idx / NC, j = idx % NC;
        float v;
        if (k < 64) {
            const float* W = (j < 128) ? Wxz : (j < 256) ? Wxr : Wxh;
            v = W[k * 128 + (j & 127)];
        } else {
            const float* W = (j < 128) ? Wmz : (j < 256) ? Wmr : Wmh;
            v = W[(k - 64) * 128 + (j & 127)];
        }
        g_Wcat[idx] = v;
    }
    if (idx < NC)
        g_bias[idx] = (idx < 128) ? bmz[idx] : (idx < 256) ? 0.f : bmh[idx - 256];
}

// ============================ K4: U GEMM =====================================
// U = XM @ Wcat + bias : M=256000, K=128, N=384
#define K4_ROWS 32
#define K4_SMEM ((128*NC + NC + K4_ROWS*128) * 4)
__global__ void k4_ugemm() {
    extern __shared__ float sm[];
    float* Ws = sm;                    // [128][384]
    float* bs = Ws + 128 * NC;         // [384]
    float* As = bs + NC;               // [32][128]
    int tid = threadIdx.x;

    for (int idx = tid; idx < 128 * NC / 4; idx += 256)
        *(float4*)(Ws + idx * 4) = *(const float4*)(g_Wcat + idx * 4);
    for (int j = tid; j < NC; j += 256) bs[j] = g_bias[j];

    int row0 = blockIdx.x * K4_ROWS;
    const float* A = g_XM + (size_t)row0 * 128;
    for (int idx = tid; idx < K4_ROWS * 128 / 4; idx += 256)
        *(float4*)(As + idx * 4) = *(const float4*)(A + idx * 4);
    __syncthreads();

    int cg = tid & 31;           // 32 col groups of 12
    int rg = tid >> 5;           // 8 row groups of 4
    int j0 = cg * 12, r0 = rg * 4;

    float acc[4][12];
    #pragma unroll
    for (int r = 0; r < 4; r++)
        #pragma unroll
        for (int c = 0; c < 12; c++) acc[r][c] = 0.f;

    #pragma unroll 4
    for (int k = 0; k < 128; k++) {
        float a0 = As[(r0 + 0) * 128 + k];
        float a1 = As[(r0 + 1) * 128 + k];
        float a2 = As[(r0 + 2) * 128 + k];
        float a3 = As[(r0 + 3) * 128 + k];
        const float* wrow = Ws + k * NC + j0;
        float4 w0 = *(const float4*)(wrow + 0);
        float4 w1 = *(const float4*)(wrow + 4);
        float4 w2 = *(const float4*)(wrow + 8);
        float w[12] = {w0.x, w0.y, w0.z, w0.w, w1.x, w1.y, w1.z, w1.w,
                       w2.x, w2.y, w2.z, w2.w};
        #pragma unroll
        for (int c = 0; c < 12; c++) {
            acc[0][c] += a0 * w[c];
            acc[1][c] += a1 * w[c];
            acc[2][c] += a2 * w[c];
            acc[3][c] += a3 * w[c];
        }
    }

    float* Ubase = g_U + (size_t)row0 * NC;
    #pragma unroll
    for (int r = 0; r < 4; r++)
        #pragma unroll
        for (int c = 0; c < 12; c++)
            Ubase[(size_t)(r0 + r) * NC + j0 + c] = acc[r][c] + bs[j0 + c];
}

// ============================ K5: sequential recurrence ======================
// 128 CTAs x 2 batch rows, 512 threads. W_hz|W_hr|W_hh resident in SMEM.
#define HSTR 132
#define K5_SMEM ((128*NC + 3*2*HSTR) * 4)
__global__ void k5_rec(const float* __restrict__ Whz, const float* __restrict__ Whr,
                       const float* __restrict__ Whh, float* __restrict__ hs_out) {
    extern __shared__ float sm[];
    float* Ws   = sm;                        // [128][384]  (k-major)
    float* h_s  = Ws + 128 * NC;             // [2][HSTR]
    float* rh_s = h_s + 2 * HSTR;            // [2][HSTR]
    float* ht_s = rh_s + 2 * HSTR;           // [2][HSTR]
    int tid = threadIdx.x;
    int b0  = blockIdx.x * 2;

    for (int idx = tid; idx < 128 * 128; idx += 512) {
        int k = idx >> 7, j = idx & 127;
        Ws[k * NC + j]       = Whz[idx];
        Ws[k * NC + 128 + j] = Whr[idx];
        Ws[k * NC + 256 + j] = Whh[idx];
    }
    if (tid < 256) h_s[(tid >> 7) * HSTR + (tid & 127)] = 0.f;
    __syncthreads();

    int grp = (tid < 256) ? 0 : 1;
    int lt  = tid & 255;
    int role_row = lt & 1;
    int role_j   = lt >> 1;

    // prefetched values
    float gh = 0.f, u_r = 0.f, u_h = 0.f, u_z = 0.f;
    if (grp == 0) {
        gh  = g_GH[((b0 + (tid >> 7)) << 7) + (tid & 127)];
        u_r = g_U[(size_t)(b0 + role_row) * NC + 128 + role_j];
        u_h = g_U[(size_t)(b0 + role_row) * NC + 256 + role_j];
    } else {
        u_z = g_U[(size_t)(b0 + role_row) * NC + role_j];
    }

    for (int t = 0; t < TT; t++) {
        int tn = (t + 1 < TT) ? (t + 1) : t;
        // (a) scale h by gamma_h
        if (grp == 0) {
            int sr = tid >> 7, sj = tid & 127;
            h_s[sr * HSTR + sj] *= gh;
        }
        __syncthreads();
        if (grp == 0)
            gh = g_GH[((tn * BB + b0 + (tid >> 7)) << 7) + (tid & 127)];

        float zval = 0.f, hold = 0.f;
        if (grp == 0) {
            // r gate -> rh
            const float* hrow = h_s + role_row * HSTR;
            const float* wc   = Ws + 128 + role_j;
            float acc = 0.f;
            #pragma unroll 16
            for (int k = 0; k < 128; k++) acc += hrow[k] * wc[k * NC];
            acc += u_r;
            float r = 1.f / (1.f + __expf(-acc));
            rh_s[role_row * HSTR + role_j] = r * hrow[role_j];
            u_r = g_U[(size_t)(tn * BB + b0 + role_row) * NC + 128 + role_j];
        } else {
            // z gate
            const float* hrow = h_s + role_row * HSTR;
            const float* wc   = Ws + role_j;
            float acc = 0.f;
            #pragma unroll 16
            for (int k = 0; k < 128; k++) acc += hrow[k] * wc[k * NC];
            acc += u_z;
            zval = 1.f / (1.f + __expf(-acc));
            hold = hrow[role_j];
            u_z = g_U[(size_t)(tn * BB + b0 + role_row) * NC + role_j];
        }
        __syncthreads();
        if (grp == 0) {
            // h~ = tanh(U_h + (r*h) @ W_hh)
            const float* rrow = rh_s + role_row * HSTR;
            const float* wc   = Ws + 256 + role_j;
            float acc = 0.f;
            #pragma unroll 16
            for (int k = 0; k < 128; k++) acc += rrow[k] * wc[k * NC];
            acc += u_h;
            ht_s[role_row * HSTR + role_j] = tanhf(acc);
            u_h = g_U[(size_t)(tn * BB + b0 + role_row) * NC + 256 + role_j];
        }
        __syncthreads();
        if (grp == 1) {
            float ht = ht_s[role_row * HSTR + role_j];
            float hn = (1.f - zval) * hold + zval * ht;
            h_s[role_row * HSTR + role_j] = hn;
            hs_out[((size_t)(b0 + role_row) * TT + t) * HID + role_j] = hn;
        }
        __syncthreads();
    }
}

// ============================ K6: y epilogue GEMM ============================
__global__ void k6_y(const float* __restrict__ Why, const float* __restrict__ bhy,
                     const float* __restrict__ hs, float* __restrict__ ys) {
    __shared__ float Ws[128 * 64];
    __shared__ float bs[64];
    __shared__ float As[16 * 128];
    int tid = threadIdx.x;
    for (int idx = tid; idx < 128 * 64; idx += 256) Ws[idx] = Why[idx];
    if (tid < 64) bs[tid] = bhy[tid];
    int row0 = blockIdx.x * 16;
    for (int idx = tid; idx < 16 * 128 / 4; idx += 256)
        *(float4*)(As + idx * 4) = *(const float4*)(hs + (size_t)row0 * 128 + idx * 4);
    __syncthreads();

    int col = tid & 63, rg = tid >> 6;   // 4 row groups of 4 rows
    float a0 = 0.f, a1 = 0.f, a2 = 0.f, a3 = 0.f;
    #pragma unroll 8
    for (int k = 0; k < 128; k++) {
        float w = Ws[k * 64 + col];
        a0 += As[(rg * 4 + 0) * 128 + k] * w;
        a1 += As[(rg * 4 + 1) * 128 + k] * w;
        a2 += As[(rg * 4 + 2) * 128 + k] * w;
        a3 += As[(rg * 4 + 3) * 128 + k] * w;
    }
    float b = bs[col];
    size_t obase = (size_t)(row0 + rg * 4) * 64 + col;
    ys[obase + 0 * 64] = 1.f / (1.f + __expf(-(a0 + b)));
    ys[obase + 1 * 64] = 1.f / (1.f + __expf(-(a1 + b)));
    ys[obase + 2 * 64] = 1.f / (1.f + __expf(-(a2 + b)));
    ys[obase + 3 * 64] = 1.f / (1.f + __expf(-(a3 + b)));
}

// ============================ launch =========================================
extern "C" void kernel_launch(void* const* d_in, const int* in_sizes, int n_in,
                              void* d_out, int out_size) {
    const float* inp   = (const float*)d_in[0];
    const float* xmean = (const float*)d_in[1];
    const float* Wdgx  = (const float*)d_in[2];
    const float* bdgx  = (const float*)d_in[3];
    const float* Wdgh  = (const float*)d_in[4];
    const float* bdgh  = (const float*)d_in[5];
    const float* Wxz   = (const float*)d_in[6];
    const float* Whz   = (const float*)d_in[7];
    const float* Wmz   = (const float*)d_in[8];
    const float* bmz   = (const float*)d_in[9];
    const float* Wxr   = (const float*)d_in[10];
    const float* Whr   = (const float*)d_in[11];
    const float* Wmr   = (const float*)d_in[12];
    const float* Wxh   = (const float*)d_in[13];
    const float* Whh   = (const float*)d_in[14];
    const float* Wmh   = (const float*)d_in[15];
    const float* bmh   = (const float*)d_in[16];
    const float* Why   = (const float*)d_in[17];
    const float* bhy   = (const float*)d_in[18];

    float* ys = (float*)d_out;                              // (B, T, 64)
    float* hs = (float*)d_out + (size_t)BB * TT * NOUT;     // (B, T, 128)

    cudaFuncSetAttribute(k1_gamma, cudaFuncAttributeMaxDynamicSharedMemorySize, K1_SMEM);
    cudaFuncSetAttribute(k4_ugemm, cudaFuncAttributeMaxDynamicSharedMemorySize, K4_SMEM);
    cudaFuncSetAttribute(k5_rec,   cudaFuncAttributeMaxDynamicSharedMemorySize, K5_SMEM);

    k1_gamma<<<dim3(TT / K1_T, BB), 256, K1_SMEM>>>(inp, Wdgx, bdgx, Wdgh, bdgh);
    k2_scan<<<64, 256>>>(inp, xmean);
    k_pack<<<(128 * NC + 255) / 256, 256>>>(Wxz, Wmz, bmz, Wxr, Wmr, Wxh, Wmh, bmh);
    k4_ugemm<<<TT * BB / K4_ROWS, 256, K4_SMEM>>>();
    k5_rec<<<BB / 2, 512, K5_SMEM>>>(Whz, Whr, Whh, hs);
    k6_y<<<TT * BB / 16, 256>>>(Why, bhy, hs, ys);
}

// round 10
// speedup vs baseline: 1.0031x; 1.0015x over previous
#include <cuda_runtime.h>
#include <math.h>

#define BB   256
#define NIN  64
#define HID  128
#define NOUT 64
#define TT   1000
#define NC   384   // z(128) | r(128) | h~(128)

// ---------------- scratch (static device memory; no allocations) -------------
__device__ float g_GX[TT * BB * NIN];          //  65.5 MB  gamma_x  [(t*B+b)*64 + i]
__device__ float g_GH[TT * BB * HID];          // 131.1 MB  gamma_h  [(t*B+b)*128 + j]
__device__ float g_XM[TT * BB * 128];          // 131.1 MB  [x_hat(64) | m(64)] per (t,b)
__device__ float g_U [TT * BB * NC];           // 393.2 MB  input projections
__device__ float g_Wcat[128 * NC];             // packed [x;m] -> [z|r|h~] weights
__device__ float g_bias[NC];

// ============================ K1: gamma GEMM =================================
// gamma = exp(-relu(d @ [W_dg_x | W_dg_h] + bias)), rows are (b,t) pairs.
#define K1_T 40
#define K1_SMEM ((64*192 + 192 + 64*K1_T) * 4)
__global__ void k1_gamma(const float* __restrict__ inp,
                         const float* __restrict__ Wdgx, const float* __restrict__ bdgx,
                         const float* __restrict__ Wdgh, const float* __restrict__ bdgh) {
    extern __shared__ float sm[];
    float* Wg   = sm;               // [64][192]
    float* bias = Wg + 64 * 192;    // [192]
    float* ds   = bias + 192;       // [64][K1_T]
    int tid = threadIdx.x;
    int b   = blockIdx.y;
    int t0  = blockIdx.x * K1_T;

    for (int idx = tid; idx < 64 * 192; idx += 256) {
        int k = idx / 192, j = idx % 192;
        Wg[idx] = (j < 64) ? Wdgx[k * 64 + j] : Wdgh[k * 128 + (j - 64)];
    }
    for (int j = tid; j < 192; j += 256)
        bias[j] = (j < 64) ? bdgx[j] : bdgh[j - 64];

    const float* dbase = inp + ((size_t)(b * 3 + 2) * NIN) * TT;
    for (int idx = tid; idx < 64 * (K1_T / 4); idx += 256) {
        int i = idx / (K1_T / 4), c = idx % (K1_T / 4);
        float4 v = *(const float4*)(dbase + (size_t)i * TT + t0 + c * 4);
        *(float4*)(ds + i * K1_T + c * 4) = v;
    }
    __syncthreads();

    for (int o = tid; o < K1_T * 192; o += 256) {
        int tt = o / 192, j = o % 192;
        float acc = bias[j];
        #pragma unroll 16
        for (int k = 0; k < 64; k++)
            acc += ds[k * K1_T + tt] * Wg[k * 192 + j];
        float g = (acc > 0.f) ? __expf(-acc) : 1.f;
        int t = t0 + tt;
        if (j < 64) g_GX[((t * BB + b) << 6) + j] = g;
        else        g_GH[((t * BB + b) << 7) + (j - 64)] = g;
    }
}

// ============================ K2: xl scan + x_hat ============================
__global__ void k2_scan(const float* __restrict__ inp, const float* __restrict__ xmean) {
    int gid = blockIdx.x * blockDim.x + threadIdx.x;   // 0..16383
    int b = gid >> 6, i = gid & 63;
    const float* X = inp + ((size_t)(b * 3 + 0) * NIN + i) * TT;
    const float* M = inp + ((size_t)(b * 3 + 1) * NIN + i) * TT;
    float xm = xmean[i];
    float xl = 0.f;
    for (int t = 0; t < TT; t++) {
        float x = X[t], m = M[t];
        float gx = g_GX[((t * BB + b) << 6) + i];
        if (m > 0.f) xl = x;
        float xh = m * x + (1.f - m) * (gx * xl + (1.f - gx) * xm);
        int base = ((t * BB + b) << 7);
        g_XM[base + i]      = xh;
        g_XM[base + 64 + i] = m;
    }
}

// ============================ K3: weight packing =============================
__global__ void k_pack(const float* __restrict__ Wxz, const float* __restrict__ Wmz,
                       const float* __restrict__ bmz,
                       const float* __restrict__ Wxr, const float* __restrict__ Wmr,
                       const float* __restrict__ Wxh, const float* __restrict__ Wmh,
                       const float* __restrict__ bmh) {
    int idx = blockIdx.x * 256 + threadIdx.x;
    if (idx < 128 * NC) {
        int k = idx / NC, j = idx % NC;
        float v;
        if (k < 64) {
            const float* W = (j < 128) ? Wxz : (j < 256) ? Wxr : Wxh;
            v = W[k * 128 + (j & 127)];
        } else {
            const float* W = (j < 128) ? Wmz : (j < 256) ? Wmr : Wmh;
            v = W[(k - 64) * 128 + (j & 127)];
        }
        g_Wcat[idx] = v;
    }
    if (idx < NC)
        g_bias[idx] = (idx < 128) ? bmz[idx] : (idx < 256) ? 0.f : bmh[idx - 256];
}

// ============================ K4: U GEMM =====================================
// U = XM @ Wcat + bias : M=256000, K=128, N=384
#define K4_ROWS 32
#define K4_SMEM ((128*NC + NC + K4_ROWS*128) * 4)
__global__ void k4_ugemm() {
    extern __shared__ float sm[];
    float* Ws = sm;                    // [128][384]
    float* bs = Ws + 128 * NC;         // [384]
    float* As = bs + NC;               // [32][128]
    int tid = threadIdx.x;

    for (int idx = tid; idx < 128 * NC / 4; idx += 256)
        *(float4*)(Ws + idx * 4) = *(const float4*)(g_Wcat + idx * 4);
    for (int j = tid; j < NC; j += 256) bs[j] = g_bias[j];

    int row0 = blockIdx.x * K4_ROWS;
    const float* A = g_XM + (size_t)row0 * 128;
    for (int idx = tid; idx < K4_ROWS * 128 / 4; idx += 256)
        *(float4*)(As + idx * 4) = *(const float4*)(A + idx * 4);
    __syncthreads();

    int cg = tid & 31;           // 32 col groups of 12
    int rg = tid >> 5;           // 8 row groups of 4
    int j0 = cg * 12, r0 = rg * 4;

    float acc[4][12];
    #pragma unroll
    for (int r = 0; r < 4; r++)
        #pragma unroll
        for (int c = 0; c < 12; c++) acc[r][c] = 0.f;

    #pragma unroll 4
    for (int k = 0; k < 128; k++) {
        float a0 = As[(r0 + 0) * 128 + k];
        float a1 = As[(r0 + 1) * 128 + k];
        float a2 = As[(r0 + 2) * 128 + k];
        float a3 = As[(r0 + 3) * 128 + k];
        const float* wrow = Ws + k * NC + j0;
        float4 w0 = *(const float4*)(wrow + 0);
        float4 w1 = *(const float4*)(wrow + 4);
        float4 w2 = *(const float4*)(wrow + 8);
        float w[12] = {w0.x, w0.y, w0.z, w0.w, w1.x, w1.y, w1.z, w1.w,
                       w2.x, w2.y, w2.z, w2.w};
        #pragma unroll
        for (int c = 0; c < 12; c++) {
            acc[0][c] += a0 * w[c];
            acc[1][c] += a1 * w[c];
            acc[2][c] += a2 * w[c];
            acc[3][c] += a3 * w[c];
        }
    }

    float* Ubase = g_U + (size_t)row0 * NC;
    #pragma unroll
    for (int r = 0; r < 4; r++)
        #pragma unroll
        for (int c = 0; c < 12; c++)
            Ubase[(size_t)(r0 + r) * NC + j0 + c] = acc[r][c] + bs[j0 + c];
}

// ============================ K5: sequential recurrence ======================
// 128 CTAs x 2 batch rows, 512 threads. W_hz|W_hr|W_hh resident in SMEM.
#define HSTR 132
#define K5_SMEM ((128*NC + 3*2*HSTR) * 4)
__global__ void k5_rec(const float* __restrict__ Whz, const float* __restrict__ Whr,
                       const float* __restrict__ Whh, float* __restrict__ hs_out) {
    extern __shared__ float sm[];
    float* Ws   = sm;                        // [128][384]  (k-major)
    float* h_s  = Ws + 128 * NC;             // [2][HSTR]
    float* rh_s = h_s + 2 * HSTR;            // [2][HSTR]
    float* ht_s = rh_s + 2 * HSTR;           // [2][HSTR]
    int tid = threadIdx.x;
    int b0  = blockIdx.x * 2;

    for (int idx = tid; idx < 128 * 128; idx += 512) {
        int k = idx >> 7, j = idx & 127;
        Ws[k * NC + j]       = Whz[idx];
        Ws[k * NC + 128 + j] = Whr[idx];
        Ws[k * NC + 256 + j] = Whh[idx];
    }
    if (tid < 256) h_s[(tid >> 7) * HSTR + (tid & 127)] = 0.f;
    __syncthreads();

    int grp = (tid < 256) ? 0 : 1;
    int lt  = tid & 255;
    int role_row = lt & 1;
    int role_j   = lt >> 1;

    // prefetched values
    float gh = 0.f, u_r = 0.f, u_h = 0.f, u_z = 0.f;
    if (grp == 0) {
        gh  = g_GH[((b0 + (tid >> 7)) << 7) + (tid & 127)];
        u_r = g_U[(size_t)(b0 + role_row) * NC + 128 + role_j];
        u_h = g_U[(size_t)(b0 + role_row) * NC + 256 + role_j];
    } else {
        u_z = g_U[(size_t)(b0 + role_row) * NC + role_j];
    }

    for (int t = 0; t < TT; t++) {
        int tn = (t + 1 < TT) ? (t + 1) : t;
        // (a) scale h by gamma_h
        if (grp == 0) {
            int sr = tid >> 7, sj = tid & 127;
            h_s[sr * HSTR + sj] *= gh;
        }
        __syncthreads();
        if (grp == 0)
            gh = g_GH[((tn * BB + b0 + (tid >> 7)) << 7) + (tid & 127)];

        float zval = 0.f, hold = 0.f;
        if (grp == 0) {
            // r gate -> rh
            const float* hrow = h_s + role_row * HSTR;
            const float* wc   = Ws + 128 + role_j;
            float acc = 0.f;
            #pragma unroll 16
            for (int k = 0; k < 128; k++) acc += hrow[k] * wc[k * NC];
            acc += u_r;
            float r = 1.f / (1.f + __expf(-acc));
            rh_s[role_row * HSTR + role_j] = r * hrow[role_j];
            u_r = g_U[(size_t)(tn * BB + b0 + role_row) * NC + 128 + role_j];
        } else {
            // z gate
            const float* hrow = h_s + role_row * HSTR;
            const float* wc   = Ws + role_j;
            float acc = 0.f;
            #pragma unroll 16
            for (int k = 0; k < 128; k++) acc += hrow[k] * wc[k * NC];
            acc += u_z;
            zval = 1.f / (1.f + __expf(-acc));
            hold = hrow[role_j];
            u_z = g_U[(size_t)(tn * BB + b0 + role_row) * NC + role_j];
        }
        __syncthreads();
        if (grp == 0) {
            // h~ = tanh(U_h + (r*h) @ W_hh)
            const float* rrow = rh_s + role_row * HSTR;
            const float* wc   = Ws + 256 + role_j;
            float acc = 0.f;
            #pragma unroll 16
            for (int k = 0; k < 128; k++) acc += rrow[k] * wc[k * NC];
            acc += u_h;
            ht_s[role_row * HSTR + role_j] = tanhf(acc);
            u_h = g_U[(size_t)(tn * BB + b0 + role_row) * NC + 256 + role_j];
        }
        __syncthreads();
        if (grp == 1) {
            float ht = ht_s[role_row * HSTR + role_j];
            float hn = (1.f - zval) * hold + zval * ht;
            h_s[role_row * HSTR + role_j] = hn;
            hs_out[((size_t)(b0 + role_row) * TT + t) * HID + role_j] = hn;
        }
        __syncthreads();
    }
}

// ============================ K6: y epilogue GEMM ============================
__global__ void k6_y(const float* __restrict__ Why, const float* __restrict__ bhy,
                     const float* __restrict__ hs, float* __restrict__ ys) {
    __shared__ float Ws[128 * 64];
    __shared__ float bs[64];
    __shared__ float As[16 * 128];
    int tid = threadIdx.x;
    for (int idx = tid; idx < 128 * 64; idx += 256) Ws[idx] = Why[idx];
    if (tid < 64) bs[tid] = bhy[tid];
    int row0 = blockIdx.x * 16;
    for (int idx = tid; idx < 16 * 128 / 4; idx += 256)
        *(float4*)(As + idx * 4) = *(const float4*)(hs + (size_t)row0 * 128 + idx * 4);
    __syncthreads();

    int col = tid & 63, rg = tid >> 6;   // 4 row groups of 4 rows
    float a0 = 0.f, a1 = 0.f, a2 = 0.f, a3 = 0.f;
    #pragma unroll 8
    for (int k = 0; k < 128; k++) {
        float w = Ws[k * 64 + col];
        a0 += As[(rg * 4 + 0) * 128 + k] * w;
        a1 += As[(rg * 4 + 1) * 128 + k] * w;
        a2 += As[(rg * 4 + 2) * 128 + k] * w;
        a3 += As[(rg * 4 + 3) * 128 + k] * w;
    }
    float b = bs[col];
    size_t obase = (size_t)(row0 + rg * 4) * 64 + col;
    ys[obase + 0 * 64] = 1.f / (1.f + __expf(-(a0 + b)));
    ys[obase + 1 * 64] = 1.f / (1.f + __expf(-(a1 + b)));
    ys[obase + 2 * 64] = 1.f / (1.f + __expf(-(a2 + b)));
    ys[obase + 3 * 64] = 1.f / (1.f + __expf(-(a3 + b)));
}

// ============================ launch =========================================
extern "C" void kernel_launch(void* const* d_in, const int* in_sizes, int n_in,
                              void* d_out, int out_size) {
    const float* inp   = (const float*)d_in[0];
    const float* xmean = (const float*)d_in[1];
    const float* Wdgx  = (const float*)d_in[2];
    const float* bdgx  = (const float*)d_in[3];
    const float* Wdgh  = (const float*)d_in[4];
    const float* bdgh  = (const float*)d_in[5];
    const float* Wxz   = (const float*)d_in[6];
    const float* Whz   = (const float*)d_in[7];
    const float* Wmz   = (const float*)d_in[8];
    const float* bmz   = (const float*)d_in[9];
    const float* Wxr   = (const float*)d_in[10];
    const float* Whr   = (const float*)d_in[11];
    const float* Wmr   = (const float*)d_in[12];
    const float* Wxh   = (const float*)d_in[13];
    const float* Whh   = (const float*)d_in[14];
    const float* Wmh   = (const float*)d_in[15];
    const float* bmh   = (const float*)d_in[16];
    const float* Why   = (const float*)d_in[17];
    const float* bhy   = (const float*)d_in[18];

    float* ys = (float*)d_out;                              // (B, T, 64)
    float* hs = (float*)d_out + (size_t)BB * TT * NOUT;     // (B, T, 128)

    cudaFuncSetAttribute(k1_gamma, cudaFuncAttributeMaxDynamicSharedMemorySize, K1_SMEM);
    cudaFuncSetAttribute(k4_ugemm, cudaFuncAttributeMaxDynamicSharedMemorySize, K4_SMEM);
    cudaFuncSetAttribute(k5_rec,   cudaFuncAttributeMaxDynamicSharedMemorySize, K5_SMEM);

    k1_gamma<<<dim3(TT / K1_T, BB), 256, K1_SMEM>>>(inp, Wdgx, bdgx, Wdgh, bdgh);
    k2_scan<<<64, 256>>>(inp, xmean);
    k_pack<<<(128 * NC + 255) / 256, 256>>>(Wxz, Wmz, bmz, Wxr, Wmr, Wxh, Wmh, bmh);
    k4_ugemm<<<TT * BB / K4_ROWS, 256, K4_SMEM>>>();
    k5_rec<<<BB / 2, 512, K5_SMEM>>>(Whz, Whr, Whh, hs);
    k6_y<<<TT * BB / 16, 256>>>(Why, bhy, hs, ys);
}